// round 17
// baseline (speedup 1.0000x reference)
#include <cuda_runtime.h>
#include <cuda_bf16.h>
#include <cstdint>
#include <cfloat>

#define NMAX 100000
#define BMAX 64
#define DD   256
#define TT   4
#define HH   32
#define K2CH 256
#define K3CH 512

// ---------------- scratch ----------------------------------------------------
__device__ float         g_targets[BMAX * DD];
__device__ unsigned      g_tbits[BMAX * 4];
__device__ unsigned      g_abits[NMAX * 4];
__device__ unsigned char g_dist_t[(size_t)NMAX * BMAX];
__device__ unsigned      g_hist[BMAX * 129];
__device__ int           g_dstar[BMAX];
__device__ int           g_r[BMAX];
__device__ int           g_istar[BMAX];
__device__ unsigned      g_cnt[200 * BMAX];
__device__ float         g_scores[(size_t)BMAX * NMAX];
__device__ float         g_pv[BMAX * 16 * 10];
__device__ int           g_pi[BMAX * 16 * 10];
__device__ unsigned      g_projs[3 * 2 * 8192];   // [s*2+h][col][kpair] bf16x2

__device__ __forceinline__ unsigned smem_u32(const void* p) {
    unsigned a;
    asm("{ .reg .u64 t; cvta.to.shared.u64 t, %1; cvt.u32.u64 %0, t; }"
        : "=r"(a) : "l"(p));
    return a;
}
// one bf16 split step on a pair: returns packed bf16x2, subtracts from residuals
__device__ __forceinline__ unsigned split_pack(float& x0, float& x1) {
    __nv_bfloat16 b0 = __float2bfloat16(x0), b1 = __float2bfloat16(x1);
    x0 -= __bfloat162float(b0);
    x1 -= __bfloat162float(b1);
    unsigned short u0 = *(unsigned short*)&b0, u1 = *(unsigned short*)&b1;
    return (unsigned)u0 | ((unsigned)u1 << 16);
}

// ---------------- K0m: targets + zero hist (launch idx 0) -------------------
__global__ void k0m_targets(const int* __restrict__ head,
                            const int* __restrict__ rel,
                            const float* __restrict__ eemb,
                            const float* __restrict__ remb)
{
    int b = blockIdx.x, tid = threadIdx.x;
    int hh = head[b], rr = rel[b];
    for (int d = tid; d < DD; d += blockDim.x)
        g_targets[b * DD + d] = eemb[(size_t)hh * DD + d] * remb[(size_t)rr * DD + d];
    for (int i = tid; i < 129; i += blockDim.x) g_hist[b * 129 + i] = 0u;
}

// ---------------- K0b: target hash bits (launch idx 1) ----------------------
__global__ void k0b_tbits(const float* __restrict__ proj)
{
    __shared__ float tgt[DD];
    int b = blockIdx.x, tid = threadIdx.x;
    for (int d = tid; d < DD; d += blockDim.x) tgt[d] = g_targets[b * DD + d];
    __syncthreads();
    int t = tid >> 5, lane = tid & 31;
    const float* pp = proj + (size_t)t * DD * HH + lane;
    float acc = 0.f;
#pragma unroll 8
    for (int d = 0; d < DD; d++) acc += tgt[d] * pp[d * HH];
    unsigned w = __ballot_sync(0xffffffffu, acc > 0.f);
    if (lane == 0) g_tbits[b * 4 + t] = w;
}

// ---------------- K0p: proj -> 3-way bf16 split planes (launch idx 2) -------
// g_projs[(s*2+h)*8192 + col*64 + kp] = bf16x2 of split s, k = h*128 + 2kp
__global__ void k0p_split(const float* __restrict__ proj)
{
    int idx = blockIdx.x * 256 + threadIdx.x;
    if (idx >= 3 * 2 * 8192) return;
    int sh = idx >> 13;           // s*2 + h
    int s  = sh >> 1, h = sh & 1;
    int r  = idx & 8191;
    int col = r >> 6, kp = r & 63;
    int t = col >> 5, hh = col & 31;
    int d0 = h * 128 + kp * 2;
    float x0 = proj[(size_t)t * 8192 + (size_t)d0 * 32 + hh];
    float x1 = proj[(size_t)t * 8192 + (size_t)(d0 + 1) * 32 + hh];
    unsigned u = 0;
    for (int k = 0; k <= s; k++) u = split_pack(x0, x1);
    g_projs[idx] = u;
}

// ---------------- K1: legacy bf16 mma.sync GEMM (launch idx 3, profiled) ----
// D[m=entity(128)][n=proj col(128)] over K=256 (2 halves), 6 split products.
// smem: ent planes @0/32768/65536, proj planes @98304/131072/163840 (192KB).
// Swizzle: off ^= ((off>>8)&7)<<4  (row low bits -> 16B block bits).
__global__ __launch_bounds__(256, 1)
void k1_tc(const float* __restrict__ eemb, int N)
{
    extern __shared__ unsigned char sm[];
    unsigned smb = smem_u32(sm);
    int tid = threadIdx.x, w = tid >> 5, lane = tid & 31;
    int m0 = w * 16;

    // ldmatrix lane constants (swizzle XOR depends only on lane)
    int rowA = m0 + (lane & 7) + ((lane >> 3) & 1) * 8;
    unsigned baseA = (unsigned)(rowA * 256 + ((lane >> 4) & 1) * 16);
    unsigned swzA  = (unsigned)((rowA & 7) << 4);
    unsigned baseB = (unsigned)(98304 + (lane & 7) * 256 + ((lane >> 3) & 1) * 16);
    unsigned swzB  = (unsigned)((lane & 7) << 4);

    int tiles = (N + 127) >> 7;
    int per = (tiles + gridDim.x - 1) / gridDim.x;
    int t0 = blockIdx.x * per, t1 = min(tiles, t0 + per);
    if (t0 >= t1) return;

    for (int tile = t0; tile < t1; tile++) {
        int base = tile * 128;
        int cnt = min(128, N - base);

        float acc[64];
#pragma unroll
        for (int i = 0; i < 64; i++) acc[i] = 0.f;

        for (int h = 0; h < 2; h++) {
            // stage proj split planes for this k-half (L2-resident copy)
            for (int idx = tid; idx < 24576; idx += 256) {
                int s = idx >> 13, r = idx & 8191;
                int col = r >> 6, kp = r & 63;
                unsigned u = g_projs[(s * 2 + h) * 8192 + r];
                unsigned off = (unsigned)(col * 256 + kp * 4);
                off ^= ((off >> 8) & 7) << 4;
                *(unsigned*)(sm + 98304 + s * 32768 + off) = u;
            }
            // stage entity split planes (convert f32 -> 3x bf16)
            for (int idx = tid; idx < 8192; idx += 256) {
                int e = idx >> 6, kp = idx & 63;
                float x0 = 0.f, x1 = 0.f;
                if (e < cnt) {
                    float2 v = *(const float2*)(eemb + (size_t)(base + e) * DD + h * 128 + kp * 2);
                    x0 = v.x; x1 = v.y;
                }
                unsigned p0 = split_pack(x0, x1);
                unsigned p1 = split_pack(x0, x1);
                unsigned p2 = split_pack(x0, x1);
                unsigned off = (unsigned)(e * 256 + kp * 4);
                off ^= ((off >> 8) & 7) << 4;
                *(unsigned*)(sm + off)         = p0;
                *(unsigned*)(sm + 32768 + off) = p1;
                *(unsigned*)(sm + 65536 + off) = p2;
            }
            __syncthreads();

            for (int p = 0; p < 6; p++) {
                unsigned pa = (0x210100u >> (4 * p)) & 15u;   // ent split
                unsigned pb = (0x012010u >> (4 * p)) & 15u;   // proj split
                for (int ks = 0; ks < 8; ks++) {
                    unsigned a0, a1, a2, a3;
                    unsigned aaddr = smb + ((pa * 32768u + (unsigned)(ks * 32) + baseA) ^ swzA);
                    asm volatile("ldmatrix.sync.aligned.m8n8.x4.shared.b16 {%0,%1,%2,%3}, [%4];"
                        : "=r"(a0), "=r"(a1), "=r"(a2), "=r"(a3) : "r"(aaddr));
                    unsigned bb = pb * 32768u + (unsigned)(ks * 32) + baseB;
#pragma unroll
                    for (int j = 0; j < 16; j++) {
                        unsigned b0, b1;
                        unsigned baddr = smb + ((bb + (unsigned)(j * 2048)) ^ swzB);
                        asm volatile("ldmatrix.sync.aligned.m8n8.x2.shared.b16 {%0,%1}, [%2];"
                            : "=r"(b0), "=r"(b1) : "r"(baddr));
                        asm volatile(
                            "mma.sync.aligned.m16n8k16.row.col.f32.bf16.bf16.f32 "
                            "{%0,%1,%2,%3}, {%4,%5,%6,%7}, {%8,%9}, {%0,%1,%2,%3};"
                            : "+f"(acc[j * 4 + 0]), "+f"(acc[j * 4 + 1]),
                              "+f"(acc[j * 4 + 2]), "+f"(acc[j * 4 + 3])
                            : "r"(a0), "r"(a1), "r"(a2), "r"(a3), "r"(b0), "r"(b1));
                    }
                }
            }
            __syncthreads();   // before restaging next half / epilogue reuse
        }

        // epilogue: frags -> smem D[128][132], then ballot per entity
        float* sD = (float*)sm;
        int rrow = m0 + (lane >> 2);
        int ccol = (lane & 3) * 2;
#pragma unroll
        for (int j = 0; j < 16; j++) {
            *(float2*)(sD + rrow * 132 + j * 8 + ccol)       = make_float2(acc[j * 4 + 0], acc[j * 4 + 1]);
            *(float2*)(sD + (rrow + 8) * 132 + j * 8 + ccol) = make_float2(acc[j * 4 + 2], acc[j * 4 + 3]);
        }
        __syncthreads();
        for (int i = 0; i < 16; i++) {
            int e = m0 + i;
#pragma unroll
            for (int g = 0; g < 4; g++) {
                float val = sD[e * 132 + g * 32 + lane];
                unsigned bw = __ballot_sync(0xffffffffu, val > 0.f);
                if (lane == 0 && base + e < N) g_abits[(size_t)(base + e) * 4 + g] = bw;
            }
        }
        __syncthreads();
    }
}

// ---------------- K2: hamming + histograms ----------------------------------
__global__ __launch_bounds__(256)
void k2_hamming(int N)
{
    extern __shared__ unsigned char smraw[];
    uint4*         sab   = (uint4*)smraw;
    unsigned*      shist = (unsigned*)(smraw + 4096);
    unsigned char* sdist = smraw + 4096 + 33792;

    int tid = threadIdx.x, w = tid >> 5, lane = tid & 31;
    int base = blockIdx.x * K2CH;
    int cnt  = min(K2CH, N - base);

    for (int i = tid; i < BMAX * 132; i += 256) shist[i] = 0u;
    for (int i = tid; i < cnt * 4; i += 256)
        ((unsigned*)sab)[i] = g_abits[(size_t)base * 4 + i];
    __syncthreads();

    for (int q = w; q < BMAX; q += 8) {
        unsigned t0 = g_tbits[q * 4 + 0], t1 = g_tbits[q * 4 + 1];
        unsigned t2 = g_tbits[q * 4 + 2], t3 = g_tbits[q * 4 + 3];
        unsigned* hrow = shist + q * 132;
        for (int it = 0; it < K2CH / 32; it++) {
            int i = it * 32 + lane;
            uint4 a = sab[i];
            unsigned d = __popc(a.x ^ t0) + __popc(a.y ^ t1)
                       + __popc(a.z ^ t2) + __popc(a.w ^ t3);
            unsigned d2 = (i < cnt) ? d : 0xffffffffu;
            if (i < cnt) sdist[i * 68 + q] = (unsigned char)d;
            unsigned mask = __match_any_sync(0xffffffffu, d2);
            if ((int)lane == __ffs(mask) - 1 && d2 != 0xffffffffu)
                hrow[d2] = hrow[d2] + __popc(mask);
        }
    }
    __syncthreads();

    for (int idx = tid; idx < K2CH * 16; idx += 256) {
        int i = idx >> 4, c = idx & 15;
        if (i < cnt)
            ((unsigned*)g_dist_t)[((size_t)(base + i)) * 16 + c] =
                *(const unsigned*)(sdist + i * 68 + c * 4);
    }
    for (int i = tid; i < BMAX * 129; i += 256) {
        int q = i / 129, d = i - q * 129;
        unsigned v = shist[q * 132 + d];
        if (v) atomicAdd(&g_hist[i], v);
    }
}

// ---------------- K3a/b/c ---------------------------------------------------
__global__ void k3a(int CAND)
{
    __shared__ unsigned s[160];
    int q = blockIdx.x, tid = threadIdx.x;
    unsigned h = (tid < 129) ? g_hist[q * 129 + tid] : 0u;
    s[tid] = h;
    __syncthreads();
#pragma unroll
    for (int off = 1; off < 160; off <<= 1) {
        unsigned v = (tid >= off) ? s[tid - off] : 0u;
        __syncthreads();
        s[tid] += v;
        __syncthreads();
    }
    unsigned cum = s[tid];
    if (tid < 129 && cum >= (unsigned)CAND && cum - h < (unsigned)CAND) {
        g_dstar[q] = tid;
        g_r[q] = CAND - (int)(cum - h);
    }
}
__global__ __launch_bounds__(256) void k3b(int N)
{
    __shared__ unsigned char sd[K3CH * 68];
    __shared__ int sds[BMAX];
    int tid = threadIdx.x, w = tid >> 5, lane = tid & 31;
    int base = blockIdx.x * K3CH, cnt = min(K3CH, N - base);
    if (tid < BMAX) sds[tid] = g_dstar[tid];
    for (int idx = tid; idx < cnt * 16; idx += 256) {
        int i = idx >> 4, c = idx & 15;
        *(unsigned*)(sd + i * 68 + c * 4) =
            ((const unsigned*)g_dist_t)[((size_t)(base + i)) * 16 + c];
    }
    __syncthreads();
    for (int q = w; q < BMAX; q += 8) {
        int ds = sds[q]; unsigned c = 0;
        for (int it = 0; it < K3CH / 32; it++) {
            int i = it * 32 + lane;
            int f = (i < cnt) && (sd[i * 68 + q] == ds);
            c += __popc(__ballot_sync(0xffffffffu, f));
        }
        if (lane == 0) g_cnt[blockIdx.x * BMAX + q] = c;
    }
}
__global__ void k3c(int N, int nch)
{
    __shared__ unsigned scnt[256];
    __shared__ int s_c, s_rem;
    __shared__ unsigned char fl[K3CH];
    int q = blockIdx.x, tid = threadIdx.x;
    scnt[tid] = (tid < nch) ? g_cnt[tid * BMAX + q] : 0u;
    __syncthreads();
    if (tid == 0) {
        int r = g_r[q]; unsigned cum = 0; int c = 0;
        for (;; c++) {
            unsigned h = scnt[c];
            if (cum + h >= (unsigned)r) { s_c = c; s_rem = r - (int)cum; break; }
            cum += h;
        }
    }
    __syncthreads();
    int base = s_c * K3CH, ds = g_dstar[q];
    for (int i = tid; i < K3CH; i += blockDim.x) {
        int n = base + i;
        fl[i] = (n < N && g_dist_t[(size_t)n * BMAX + q] == (unsigned char)ds) ? 1 : 0;
    }
    __syncthreads();
    if (tid == 0) {
        int need = s_rem, c2 = 0, i = 0;
        for (;; i++) { c2 += fl[i]; if (c2 == need) break; }
        g_istar[q] = base + i;
    }
}

// ---------------- K4: candidate scores (persistent, 2-wide) -----------------
__global__ __launch_bounds__(256)
void k4_scores(const float* __restrict__ eemb, int N)
{
    extern __shared__ float sm4[];
    float* st   = sm4;
    float* tile = sm4 + BMAX * DD;
    int*   ds   = (int*)(tile + BMAX * 32);
    int*   is_  = ds + BMAX;

    int tid = threadIdx.x;
    for (int i = tid; i < BMAX * DD; i += blockDim.x) st[i] = g_targets[i];
    if (tid < BMAX) { ds[tid] = g_dstar[tid]; is_[tid] = g_istar[tid]; }
    __syncthreads();

    int w = tid >> 5, lane = tid & 31;
    int ntiles = (N + 31) >> 5;

    for (int tb = blockIdx.x; tb < ntiles; tb += gridDim.x) {
        int base = tb * 32;
        for (int i = tid; i < BMAX * 32; i += blockDim.x) tile[i] = -FLT_MAX;
        __syncthreads();

        for (int e = 0; e < 4; e++) {
            int i = w * 4 + e;
            int n = base + i;
            if (n >= N) continue;
            float4 r0 = *(const float4*)(eemb + (size_t)n * DD + lane * 8);
            float4 r1 = *(const float4*)(eemb + (size_t)n * DD + lane * 8 + 4);
            unsigned char d0 = g_dist_t[(size_t)n * BMAX + lane];
            unsigned char d1 = g_dist_t[(size_t)n * BMAX + 32 + lane];
            int b0 = lane, b1 = lane + 32;
            bool f0 = (d0 < ds[b0]) || (d0 == ds[b0] && n <= is_[b0]);
            bool f1 = (d1 < ds[b1]) || (d1 == ds[b1] && n <= is_[b1]);
            unsigned m0 = __ballot_sync(0xffffffffu, f0);
            unsigned m1 = __ballot_sync(0xffffffffu, f1);

            while (m0) {
                int ba = __ffs(m0) - 1; m0 &= m0 - 1;
                int bb = -1;
                if (m0) { bb = __ffs(m0) - 1; m0 &= m0 - 1; }
                int bbc = (bb >= 0) ? bb : ba;
                const float4* ta = (const float4*)(st + ba * DD + lane * 8);
                const float4* tb2 = (const float4*)(st + bbc * DD + lane * 8);
                float4 a0 = ta[0], a1 = ta[1];
                float4 c0 = tb2[0], c1 = tb2[1];
                float sa = r0.x * a0.x + r0.y * a0.y + r0.z * a0.z + r0.w * a0.w
                         + r1.x * a1.x + r1.y * a1.y + r1.z * a1.z + r1.w * a1.w;
                float sb = r0.x * c0.x + r0.y * c0.y + r0.z * c0.z + r0.w * c0.w
                         + r1.x * c1.x + r1.y * c1.y + r1.z * c1.z + r1.w * c1.w;
#pragma unroll
                for (int off = 16; off; off >>= 1) {
                    sa += __shfl_xor_sync(0xffffffffu, sa, off);
                    sb += __shfl_xor_sync(0xffffffffu, sb, off);
                }
                if (lane == 0) {
                    tile[ba * 32 + i] = sa;
                    if (bb >= 0) tile[bb * 32 + i] = sb;
                }
            }
            while (m1) {
                int ba = 32 + __ffs(m1) - 1; m1 &= m1 - 1;
                int bb = -1;
                if (m1) { bb = 32 + __ffs(m1) - 1; m1 &= m1 - 1; }
                int bbc = (bb >= 0) ? bb : ba;
                const float4* ta = (const float4*)(st + ba * DD + lane * 8);
                const float4* tb2 = (const float4*)(st + bbc * DD + lane * 8);
                float4 a0 = ta[0], a1 = ta[1];
                float4 c0 = tb2[0], c1 = tb2[1];
                float sa = r0.x * a0.x + r0.y * a0.y + r0.z * a0.z + r0.w * a0.w
                         + r1.x * a1.x + r1.y * a1.y + r1.z * a1.z + r1.w * a1.w;
                float sb = r0.x * c0.x + r0.y * c0.y + r0.z * c0.z + r0.w * c0.w
                         + r1.x * c1.x + r1.y * c1.y + r1.z * c1.z + r1.w * c1.w;
#pragma unroll
                for (int off = 16; off; off >>= 1) {
                    sa += __shfl_xor_sync(0xffffffffu, sa, off);
                    sb += __shfl_xor_sync(0xffffffffu, sb, off);
                }
                if (lane == 0) {
                    tile[ba * 32 + i] = sa;
                    if (bb >= 0) tile[bb * 32 + i] = sb;
                }
            }
        }
        __syncthreads();
        for (int idx = tid; idx < BMAX * 32; idx += blockDim.x) {
            int bb = idx >> 5, i = idx & 31;
            int n = base + i;
            if (n < N) g_scores[(size_t)bb * N + n] = tile[idx];
        }
        __syncthreads();
    }
}

// ---------------- K5a/K5b ---------------------------------------------------
#define SEG 6250
__global__ __launch_bounds__(256) void k5a(int N)
{
    extern __shared__ float sv[];
    __shared__ float wv[8]; __shared__ int wi[8];
    int b = blockIdx.x >> 4, s = blockIdx.x & 15;
    int tid = threadIdx.x, w = tid >> 5, lane = tid & 31;
    int base = s * SEG;
    const float* src = g_scores + (size_t)b * N;
    for (int i = tid; i < SEG; i += 256)
        sv[i] = (base + i < N) ? src[base + i] : -FLT_MAX;
    __syncthreads();

    for (int p = 0; p < 10; p++) {
        float bv = -FLT_MAX; int bi = 1 << 30;
        for (int i = tid; i < SEG; i += 256) {
            float v = sv[i];
            if (v > bv) { bv = v; bi = i; }
        }
#pragma unroll
        for (int off = 16; off; off >>= 1) {
            float ov = __shfl_down_sync(0xffffffffu, bv, off);
            int   oi = __shfl_down_sync(0xffffffffu, bi, off);
            if (ov > bv || (ov == bv && oi < bi)) { bv = ov; bi = oi; }
        }
        if (lane == 0) { wv[w] = bv; wi[w] = bi; }
        __syncthreads();
        if (tid == 0) {
            float fv = wv[0]; int fi = wi[0];
            for (int x = 1; x < 8; x++)
                if (wv[x] > fv || (wv[x] == fv && wi[x] < fi)) { fv = wv[x]; fi = wi[x]; }
            g_pv[blockIdx.x * 10 + p] = fv;
            g_pi[blockIdx.x * 10 + p] = base + ((fi < SEG) ? fi : 0);
            if (fi < SEG) sv[fi] = -FLT_MAX;
        }
        __syncthreads();
    }
}
__global__ void k5b(const int* __restrict__ kptr, float* __restrict__ out, int half)
{
    __shared__ float sv[160]; __shared__ int si[160];
    int b = blockIdx.x, tid = threadIdx.x;
    int kk = kptr[0];
    for (int i = tid; i < 160; i += 32) { sv[i] = g_pv[b * 160 + i]; si[i] = g_pi[b * 160 + i]; }
    __syncwarp();
    for (int p = 0; p < kk; p++) {
        float bv = -FLT_MAX; int bi = 0x7fffffff, bs = -1;
        for (int i = tid; i < 160; i += 32) {
            float v = sv[i]; int ix = si[i];
            if (v > bv || (v == bv && ix < bi)) { bv = v; bi = ix; bs = i; }
        }
#pragma unroll
        for (int off = 16; off; off >>= 1) {
            float ov = __shfl_down_sync(0xffffffffu, bv, off);
            int   oi = __shfl_down_sync(0xffffffffu, bi, off);
            int   os = __shfl_down_sync(0xffffffffu, bs, off);
            if (ov > bv || (ov == bv && oi < bi)) { bv = ov; bi = oi; bs = os; }
        }
        bs = __shfl_sync(0xffffffffu, bs, 0);
        if (tid == 0) {
            out[b * kk + p]        = (float)bi;
            out[half + b * kk + p] = bv;
            if (bs >= 0) sv[bs] = -FLT_MAX;
        }
        __syncwarp();
    }
}

// ---------------- launch ----------------------------------------------------
extern "C" void kernel_launch(void* const* d_in, const int* in_sizes, int n_in,
                              void* d_out, int out_size)
{
    const int*   head = (const int*)d_in[0];
    const int*   rel  = (const int*)d_in[1];
    const float* eemb = (const float*)d_in[2];
    const float* remb = (const float*)d_in[3];
    const float* proj = (const float*)d_in[4];
    const int*   kptr = (const int*)d_in[5];

    int B = in_sizes[0];
    int N = in_sizes[2] / DD;
    int CAND = N / 10; if (CAND < 100) CAND = 100;
    int nch2 = (N + K2CH - 1) / K2CH;
    int nch3 = (N + K3CH - 1) / K3CH;

    cudaFuncSetAttribute(k1_tc,      cudaFuncAttributeMaxDynamicSharedMemorySize, 197 * 1024);
    cudaFuncSetAttribute(k2_hamming, cudaFuncAttributeMaxDynamicSharedMemorySize, 60 * 1024);
    cudaFuncSetAttribute(k4_scores,  cudaFuncAttributeMaxDynamicSharedMemorySize, 80 * 1024);

    size_t k1_smem = 196608;                                        // 6 x 32KB planes
    size_t k2_smem = 4096 + BMAX * 132 * 4 + (size_t)K2CH * 68;     // 55296
    size_t k4_smem = (BMAX * DD + BMAX * 32) * sizeof(float) + 2 * BMAX * sizeof(int);
    size_t k5_smem = SEG * sizeof(float);

    // idx 3 = k1_tc (profiled)
    k0m_targets<<<B, 128>>>(head, rel, eemb, remb);                 // idx 0
    k0b_tbits<<<B, 128>>>(proj);                                    // idx 1
    k0p_split<<<192, 256>>>(proj);                                  // idx 2
    k1_tc<<<148, 256, k1_smem>>>(eemb, N);                          // idx 3 (profiled)
    k2_hamming<<<nch2, 256, k2_smem>>>(N);
    k3a<<<BMAX, 160>>>(CAND);
    k3b<<<nch3, 256>>>(N);
    k3c<<<BMAX, 256>>>(N, nch3);
    k4_scores<<<444, 256, k4_smem>>>(eemb, N);
    k5a<<<BMAX * 16, 256, k5_smem>>>(N);
    k5b<<<BMAX, 32>>>(kptr, (float*)d_out, out_size / 2);
}